// round 1
// baseline (speedup 1.0000x reference)
#include <cuda_runtime.h>
#include <math.h>

#define N_SEL    200000
#define EVN      100000
#define MEMD     100
#define RAWD     172
#define MSG_K    472
#define TM       64
#define MSQ      128    // msg row stride in quads (float4)
#define HSQ      32     // h row stride in quads
#define NTHREADS 256

// ---------------- device scratch (no allocations allowed) ----------------
__device__ unsigned long long g_win[N_SEL];
__device__ int g_cnt_valid;
__device__ int g_cnt_invalid;
__device__ int g_list[N_SEL];

// ---------------- kernels ----------------
__global__ void k_init() {
    int i = blockIdx.x * blockDim.x + threadIdx.x;
    if (i < N_SEL) g_win[i] = 0ull;
    if (i == 0) { g_cnt_valid = 0; g_cnt_invalid = 0; }
}

__global__ void k_aggregate(const int* __restrict__ loc_s, const int* __restrict__ t_s,
                            const int* __restrict__ loc_d, const int* __restrict__ t_d) {
    int e = blockIdx.x * blockDim.x + threadIdx.x;
    if (e >= 2 * EVN) return;
    int loc, t;
    if (e < EVN) { loc = loc_s[e];       t = t_s[e]; }
    else         { loc = loc_d[e - EVN]; t = t_d[e - EVN]; }
    // key = (t+1) in high bits (so key==0 means "no event"), event index low.
    // max over key == max over t then max event index: matches reference tie-break.
    unsigned long long key = (((unsigned long long)(unsigned)(t + 1)) << 32) | (unsigned)e;
    atomicMax(&g_win[loc], key);
}

__global__ void k_partition() {
    int i = blockIdx.x * blockDim.x + threadIdx.x;
    if (i >= N_SEL) return;
    if (g_win[i] != 0ull) { int p = atomicAdd(&g_cnt_valid, 1);   g_list[p] = i; }
    else                  { int p = atomicAdd(&g_cnt_invalid, 1); g_list[N_SEL - 1 - p] = i; }
}

__device__ __forceinline__ float dot4(float4 a, float4 b, float acc) {
    acc = fmaf(a.x, b.x, acc);
    acc = fmaf(a.y, b.y, acc);
    acc = fmaf(a.z, b.z, acc);
    acc = fmaf(a.w, b.w, acc);
    return acc;
}

__global__ __launch_bounds__(NTHREADS, 1)
void k_main(const float* __restrict__ memory, const int* __restrict__ last_update,
            const int* __restrict__ n_id,
            const int* __restrict__ dst_s, const float* __restrict__ raw_s,
            const int* __restrict__ dst_d, const float* __restrict__ raw_d,
            const float* __restrict__ time_w, const float* __restrict__ time_b,
            const float* __restrict__ W_ih, const float* __restrict__ W_hh,
            const float* __restrict__ b_ih, const float* __restrict__ b_hh,
            float* __restrict__ out_mem, float* __restrict__ out_lu, int write_lu)
{
    extern __shared__ float smf[];
    float* smsg = smf;                    // TM * 512 floats (118 quads used, swizzled)
    float* sh   = smf + TM * 512;         // TM * 128 floats (25 quads used, swizzled)
    float* sout = sh  + TM * 128;         // TM * 100 floats
    __shared__ int s_node[TM];

    const int tid  = threadIdx.x;
    const int lane = tid & 31;
    const int warp = tid >> 5;
    const int base = blockIdx.x * TM;
    const int nValid = g_cnt_valid;
    const bool doGi = (base < nValid);    // block has >=1 valid node

    // ---------------- load phase: each warp stages 8 nodes ----------------
    for (int mm = 0; mm < TM / 8; mm++) {
        int m = warp * (TM / 8) + mm;
        int i = g_list[base + m];
        if (lane == 0) s_node[m] = i;
        unsigned long long key = g_win[i];
        int gid = __ldg(&n_id[i]);
        const int s = m & 7;
        bool valid = (key != 0ull);
        const float4* hrow = (const float4*)(memory + (size_t)gid * MEMD);

        if (lane < 25) {
            float4 v = hrow[lane];
            ((float4*)sh)[m * HSQ + (lane ^ s)] = v;
            if (doGi && valid)
                ((float4*)smsg)[m * MSQ + (lane ^ s)] = v;   // z_src == h
        }
        if (doGi) {
            if (valid) {
                int e = (int)(key & 0xffffffffull);
                int t = (int)(key >> 32) - 1;
                int dst; const float* raw;
                if (e < EVN) { dst = __ldg(&dst_s[e]);           raw = raw_s + (size_t)e * RAWD; }
                else         { int e2 = e - EVN; dst = __ldg(&dst_d[e2]); raw = raw_d + (size_t)e2 * RAWD; }
                const float4* drow = (const float4*)(memory + (size_t)dst * MEMD);
                if (lane < 25)
                    ((float4*)smsg)[m * MSQ + ((25 + lane) ^ s)] = drow[lane];
                const float4* rrow = (const float4*)raw;         // e*688 bytes, 16B aligned
                for (int q = lane; q < 43; q += 32)
                    ((float4*)smsg)[m * MSQ + ((50 + q) ^ s)] = rrow[q];
                float trel = (float)(t - __ldg(&last_update[gid]));
                if (lane < 25) {
                    float4 w = ((const float4*)time_w)[lane];
                    float4 b = ((const float4*)time_b)[lane];
                    float4 te;
                    te.x = cosf(fmaf(trel, w.x, b.x));
                    te.y = cosf(fmaf(trel, w.y, b.y));
                    te.z = cosf(fmaf(trel, w.z, b.z));
                    te.w = cosf(fmaf(trel, w.w, b.w));
                    ((float4*)smsg)[m * MSQ + ((93 + lane) ^ s)] = te;
                }
            } else {
                float4 z = make_float4(0.f, 0.f, 0.f, 0.f);
                for (int q = lane; q < 118; q += 32)
                    ((float4*)smsg)[m * MSQ + (q ^ s)] = z;
            }
        }
        if (lane == 0 && write_lu) {
            int lu = __ldg(&last_update[gid]);
            if (valid) { int t = (int)(key >> 32) - 1; lu = max(lu, t); }
            out_lu[i] = (float)lu;
        }
    }
    __syncthreads();

    // ---------------- compute phase ----------------
    const int m0 = lane, m1 = lane + 32;
    const int s  = lane & 7;                          // same swizzle for m0 and m1
    const float4* aq0 = ((const float4*)smsg) + m0 * MSQ;
    const float4* aq1 = ((const float4*)smsg) + m1 * MSQ;
    const float4* hq0 = ((const float4*)sh)   + m0 * HSQ;
    const float4* hq1 = ((const float4*)sh)   + m1 * HSQ;

    for (int cp = warp; cp < 50; cp += 8) {
        const int c0 = 2 * cp, c1 = c0 + 1;
        // gi accumulators: A=node m0, B=node m1; [c][gate r/z/n]
        float A00=0.f,A01=0.f,A02=0.f, A10=0.f,A11=0.f,A12=0.f;
        float B00=0.f,B01=0.f,B02=0.f, B10=0.f,B11=0.f,B12=0.f;
        if (doGi) {
            const float4* w0r = (const float4*)(W_ih + (size_t)(      c0) * MSG_K);
            const float4* w0z = (const float4*)(W_ih + (size_t)(100 + c0) * MSG_K);
            const float4* w0n = (const float4*)(W_ih + (size_t)(200 + c0) * MSG_K);
            const float4* w1r = (const float4*)(W_ih + (size_t)(      c1) * MSG_K);
            const float4* w1z = (const float4*)(W_ih + (size_t)(100 + c1) * MSG_K);
            const float4* w1n = (const float4*)(W_ih + (size_t)(200 + c1) * MSG_K);
            #pragma unroll 2
            for (int q = 0; q < 118; q++) {
                float4 a0 = aq0[q ^ s];
                float4 a1 = aq1[q ^ s];
                float4 w;
                w = __ldg(&w0r[q]); A00 = dot4(a0, w, A00); B00 = dot4(a1, w, B00);
                w = __ldg(&w0z[q]); A01 = dot4(a0, w, A01); B01 = dot4(a1, w, B01);
                w = __ldg(&w0n[q]); A02 = dot4(a0, w, A02); B02 = dot4(a1, w, B02);
                w = __ldg(&w1r[q]); A10 = dot4(a0, w, A10); B10 = dot4(a1, w, B10);
                w = __ldg(&w1z[q]); A11 = dot4(a0, w, A11); B11 = dot4(a1, w, B11);
                w = __ldg(&w1n[q]); A12 = dot4(a0, w, A12); B12 = dot4(a1, w, B12);
            }
        }
        // gh accumulators
        float H00=0.f,H01=0.f,H02=0.f, H10=0.f,H11=0.f,H12=0.f;   // m0
        float G00=0.f,G01=0.f,G02=0.f, G10=0.f,G11=0.f,G12=0.f;   // m1
        {
            const float4* v0r = (const float4*)(W_hh + (size_t)(      c0) * MEMD);
            const float4* v0z = (const float4*)(W_hh + (size_t)(100 + c0) * MEMD);
            const float4* v0n = (const float4*)(W_hh + (size_t)(200 + c0) * MEMD);
            const float4* v1r = (const float4*)(W_hh + (size_t)(      c1) * MEMD);
            const float4* v1z = (const float4*)(W_hh + (size_t)(100 + c1) * MEMD);
            const float4* v1n = (const float4*)(W_hh + (size_t)(200 + c1) * MEMD);
            #pragma unroll 2
            for (int q = 0; q < 25; q++) {
                float4 a0 = hq0[q ^ s];
                float4 a1 = hq1[q ^ s];
                float4 w;
                w = __ldg(&v0r[q]); H00 = dot4(a0, w, H00); G00 = dot4(a1, w, G00);
                w = __ldg(&v0z[q]); H01 = dot4(a0, w, H01); G01 = dot4(a1, w, G01);
                w = __ldg(&v0n[q]); H02 = dot4(a0, w, H02); G02 = dot4(a1, w, G02);
                w = __ldg(&v1r[q]); H10 = dot4(a0, w, H10); G10 = dot4(a1, w, G10);
                w = __ldg(&v1z[q]); H11 = dot4(a0, w, H11); G11 = dot4(a1, w, G11);
                w = __ldg(&v1n[q]); H12 = dot4(a0, w, H12); G12 = dot4(a1, w, G12);
            }
        }
        // epilogue
        float bir0 = __ldg(&b_ih[c0]),       bir1 = __ldg(&b_ih[c1]);
        float biz0 = __ldg(&b_ih[100 + c0]), biz1 = __ldg(&b_ih[100 + c1]);
        float bin0 = __ldg(&b_ih[200 + c0]), bin1 = __ldg(&b_ih[200 + c1]);
        float bhr0 = __ldg(&b_hh[c0]),       bhr1 = __ldg(&b_hh[c1]);
        float bhz0 = __ldg(&b_hh[100 + c0]), bhz1 = __ldg(&b_hh[100 + c1]);
        float bhn0 = __ldg(&b_hh[200 + c0]), bhn1 = __ldg(&b_hh[200 + c1]);

        auto gate = [](float ir, float iz, float inn, float hr, float hz, float hn, float h) {
            float r = 1.f / (1.f + expf(-(ir + hr)));
            float z = 1.f / (1.f + expf(-(iz + hz)));
            float n = tanhf(fmaf(r, hn, inn));
            return fmaf(z, h - n, n);     // (1-z)*n + z*h
        };
        float h00 = sh[(m0 * HSQ + ((c0 >> 2) ^ s)) * 4 + (c0 & 3)];
        float h01 = sh[(m0 * HSQ + ((c1 >> 2) ^ s)) * 4 + (c1 & 3)];
        float h10 = sh[(m1 * HSQ + ((c0 >> 2) ^ s)) * 4 + (c0 & 3)];
        float h11 = sh[(m1 * HSQ + ((c1 >> 2) ^ s)) * 4 + (c1 & 3)];

        sout[m0 * 100 + c0] = gate(A00 + bir0, A01 + biz0, A02 + bin0, H00 + bhr0, H01 + bhz0, H02 + bhn0, h00);
        sout[m0 * 100 + c1] = gate(A10 + bir1, A11 + biz1, A12 + bin1, H10 + bhr1, H11 + bhz1, H12 + bhn1, h01);
        sout[m1 * 100 + c0] = gate(B00 + bir0, B01 + biz0, B02 + bin0, G00 + bhr0, G01 + bhz0, G02 + bhn0, h10);
        sout[m1 * 100 + c1] = gate(B10 + bir1, B11 + biz1, B12 + bin1, G10 + bhr1, G11 + bhz1, G12 + bhn1, h11);
    }
    __syncthreads();

    // coalesced scatter of output rows
    for (int idx = tid; idx < TM * 100; idx += NTHREADS) {
        int m = idx / 100, c = idx - m * 100;
        out_mem[(size_t)s_node[m] * 100 + c] = sout[idx];
    }
}

// ---------------- launch ----------------
extern "C" void kernel_launch(void* const* d_in, const int* in_sizes, int n_in,
                              void* d_out, int out_size) {
    const float* memory      = (const float*)d_in[0];
    const int*   last_update = (const int*)  d_in[1];
    const int*   n_id        = (const int*)  d_in[2];
    const int*   loc_s       = (const int*)  d_in[3];
    const int*   dst_s       = (const int*)  d_in[4];
    const int*   t_s         = (const int*)  d_in[5];
    const float* raw_s       = (const float*)d_in[6];
    const int*   loc_d       = (const int*)  d_in[7];
    const int*   dst_d       = (const int*)  d_in[8];
    const int*   t_d         = (const int*)  d_in[9];
    const float* raw_d       = (const float*)d_in[10];
    const float* time_w      = (const float*)d_in[11];
    const float* time_b      = (const float*)d_in[12];
    const float* W_ih        = (const float*)d_in[13];
    const float* W_hh        = (const float*)d_in[14];
    const float* b_ih        = (const float*)d_in[15];
    const float* b_hh        = (const float*)d_in[16];

    float* out_mem = (float*)d_out;
    float* out_lu  = out_mem + (size_t)N_SEL * MEMD;
    int write_lu = (out_size >= N_SEL * MEMD + N_SEL) ? 1 : 0;

    size_t smem = (size_t)(TM * 512 + TM * 128 + TM * 100) * sizeof(float);  // ~185 KB
    cudaFuncSetAttribute(k_main, cudaFuncAttributeMaxDynamicSharedMemorySize, (int)smem);

    k_init     <<<(N_SEL + 255) / 256, 256>>>();
    k_aggregate<<<(2 * EVN + 255) / 256, 256>>>(loc_s, t_s, loc_d, t_d);
    k_partition<<<(N_SEL + 255) / 256, 256>>>();
    k_main     <<<N_SEL / TM, NTHREADS, smem>>>(memory, last_update, n_id,
                                                dst_s, raw_s, dst_d, raw_d,
                                                time_w, time_b, W_ih, W_hh, b_ih, b_hh,
                                                out_mem, out_lu, write_lu);
}

// round 2
// speedup vs baseline: 1.0017x; 1.0017x over previous
#include <cuda_runtime.h>
#include <math.h>

#define N_SEL    200000
#define EVN      100000
#define MEMD     100
#define RAWD     172
#define MSG_K    472
#define TM       64
#define MSQ      128    // msg row stride in quads (float4)
#define HSQ      32     // h row stride in quads
#define NTHREADS 256

// ---------------- device scratch (no allocations allowed) ----------------
__device__ unsigned long long g_win[N_SEL];
__device__ int g_cnt_valid;
__device__ int g_cnt_invalid;
__device__ int g_list[N_SEL];

// ---------------- kernels ----------------
__global__ void k_init() {
    int i = blockIdx.x * blockDim.x + threadIdx.x;
    if (i < N_SEL) g_win[i] = 0ull;
    if (i == 0) { g_cnt_valid = 0; g_cnt_invalid = 0; }
}

__global__ void k_aggregate(const int* __restrict__ loc_s, const int* __restrict__ t_s,
                            const int* __restrict__ loc_d, const int* __restrict__ t_d) {
    int e = blockIdx.x * blockDim.x + threadIdx.x;
    if (e >= 2 * EVN) return;
    int loc, t;
    if (e < EVN) { loc = loc_s[e];       t = t_s[e]; }
    else         { loc = loc_d[e - EVN]; t = t_d[e - EVN]; }
    // key = (t+1) in high bits (so key==0 means "no event"), event index low.
    // max over key == max over t then max event index: matches reference tie-break.
    unsigned long long key = (((unsigned long long)(unsigned)(t + 1)) << 32) | (unsigned)e;
    atomicMax(&g_win[loc], key);
}

__global__ void k_partition() {
    int i = blockIdx.x * blockDim.x + threadIdx.x;
    if (i >= N_SEL) return;
    if (g_win[i] != 0ull) { int p = atomicAdd(&g_cnt_valid, 1);   g_list[p] = i; }
    else                  { int p = atomicAdd(&g_cnt_invalid, 1); g_list[N_SEL - 1 - p] = i; }
}

__device__ __forceinline__ float dot4(float4 a, float4 b, float acc) {
    acc = fmaf(a.x, b.x, acc);
    acc = fmaf(a.y, b.y, acc);
    acc = fmaf(a.z, b.z, acc);
    acc = fmaf(a.w, b.w, acc);
    return acc;
}

__global__ __launch_bounds__(NTHREADS, 1)
void k_main(const float* __restrict__ memory, const int* __restrict__ last_update,
            const int* __restrict__ n_id,
            const int* __restrict__ dst_s, const float* __restrict__ raw_s,
            const int* __restrict__ dst_d, const float* __restrict__ raw_d,
            const float* __restrict__ time_w, const float* __restrict__ time_b,
            const float* __restrict__ W_ih, const float* __restrict__ W_hh,
            const float* __restrict__ b_ih, const float* __restrict__ b_hh,
            float* __restrict__ out_mem, float* __restrict__ out_lu, int write_lu)
{
    extern __shared__ float smf[];
    float* smsg = smf;                    // TM * 512 floats (118 quads used, swizzled)
    float* sh   = smf + TM * 512;         // TM * 128 floats (25 quads used, swizzled)
    float* sout = sh  + TM * 128;         // TM * 100 floats
    __shared__ int s_node[TM];

    const int tid  = threadIdx.x;
    const int lane = tid & 31;
    const int warp = tid >> 5;
    const int base = blockIdx.x * TM;
    const int nValid = g_cnt_valid;
    const bool doGi = (base < nValid);    // block has >=1 valid node

    // ---------------- load phase: each warp stages 8 nodes ----------------
    for (int mm = 0; mm < TM / 8; mm++) {
        int m = warp * (TM / 8) + mm;
        int i = g_list[base + m];
        if (lane == 0) s_node[m] = i;
        unsigned long long key = g_win[i];
        int gid = __ldg(&n_id[i]);
        const int s = m & 7;
        bool valid = (key != 0ull);
        const float4* hrow = (const float4*)(memory + (size_t)gid * MEMD);

        if (lane < 25) {
            float4 v = hrow[lane];
            ((float4*)sh)[m * HSQ + (lane ^ s)] = v;
            if (doGi && valid)
                ((float4*)smsg)[m * MSQ + (lane ^ s)] = v;   // z_src == h
        }
        if (doGi) {
            if (valid) {
                int e = (int)(key & 0xffffffffull);
                int t = (int)(key >> 32) - 1;
                int dst; const float* raw;
                if (e < EVN) { dst = __ldg(&dst_s[e]);           raw = raw_s + (size_t)e * RAWD; }
                else         { int e2 = e - EVN; dst = __ldg(&dst_d[e2]); raw = raw_d + (size_t)e2 * RAWD; }
                const float4* drow = (const float4*)(memory + (size_t)dst * MEMD);
                if (lane < 25)
                    ((float4*)smsg)[m * MSQ + ((25 + lane) ^ s)] = drow[lane];
                const float4* rrow = (const float4*)raw;         // e*688 bytes, 16B aligned
                for (int q = lane; q < 43; q += 32)
                    ((float4*)smsg)[m * MSQ + ((50 + q) ^ s)] = rrow[q];
                float trel = (float)(t - __ldg(&last_update[gid]));
                if (lane < 25) {
                    float4 w = ((const float4*)time_w)[lane];
                    float4 b = ((const float4*)time_b)[lane];
                    float4 te;
                    te.x = cosf(fmaf(trel, w.x, b.x));
                    te.y = cosf(fmaf(trel, w.y, b.y));
                    te.z = cosf(fmaf(trel, w.z, b.z));
                    te.w = cosf(fmaf(trel, w.w, b.w));
                    ((float4*)smsg)[m * MSQ + ((93 + lane) ^ s)] = te;
                }
            } else {
                float4 z = make_float4(0.f, 0.f, 0.f, 0.f);
                for (int q = lane; q < 118; q += 32)
                    ((float4*)smsg)[m * MSQ + (q ^ s)] = z;
            }
        }
        if (lane == 0 && write_lu) {
            int lu = __ldg(&last_update[gid]);
            if (valid) { int t = (int)(key >> 32) - 1; lu = max(lu, t); }
            out_lu[i] = (float)lu;
        }
    }
    __syncthreads();

    // ---------------- compute phase ----------------
    const int m0 = lane, m1 = lane + 32;
    const int s  = lane & 7;                          // same swizzle for m0 and m1
    const float4* aq0 = ((const float4*)smsg) + m0 * MSQ;
    const float4* aq1 = ((const float4*)smsg) + m1 * MSQ;
    const float4* hq0 = ((const float4*)sh)   + m0 * HSQ;
    const float4* hq1 = ((const float4*)sh)   + m1 * HSQ;

    for (int cp = warp; cp < 50; cp += 8) {
        const int c0 = 2 * cp, c1 = c0 + 1;
        // gi accumulators: A=node m0, B=node m1; [c][gate r/z/n]
        float A00=0.f,A01=0.f,A02=0.f, A10=0.f,A11=0.f,A12=0.f;
        float B00=0.f,B01=0.f,B02=0.f, B10=0.f,B11=0.f,B12=0.f;
        if (doGi) {
            const float4* w0r = (const float4*)(W_ih + (size_t)(      c0) * MSG_K);
            const float4* w0z = (const float4*)(W_ih + (size_t)(100 + c0) * MSG_K);
            const float4* w0n = (const float4*)(W_ih + (size_t)(200 + c0) * MSG_K);
            const float4* w1r = (const float4*)(W_ih + (size_t)(      c1) * MSG_K);
            const float4* w1z = (const float4*)(W_ih + (size_t)(100 + c1) * MSG_K);
            const float4* w1n = (const float4*)(W_ih + (size_t)(200 + c1) * MSG_K);
            #pragma unroll 2
            for (int q = 0; q < 118; q++) {
                float4 a0 = aq0[q ^ s];
                float4 a1 = aq1[q ^ s];
                float4 w;
                w = __ldg(&w0r[q]); A00 = dot4(a0, w, A00); B00 = dot4(a1, w, B00);
                w = __ldg(&w0z[q]); A01 = dot4(a0, w, A01); B01 = dot4(a1, w, B01);
                w = __ldg(&w0n[q]); A02 = dot4(a0, w, A02); B02 = dot4(a1, w, B02);
                w = __ldg(&w1r[q]); A10 = dot4(a0, w, A10); B10 = dot4(a1, w, B10);
                w = __ldg(&w1z[q]); A11 = dot4(a0, w, A11); B11 = dot4(a1, w, B11);
                w = __ldg(&w1n[q]); A12 = dot4(a0, w, A12); B12 = dot4(a1, w, B12);
            }
        }
        // gh accumulators
        float H00=0.f,H01=0.f,H02=0.f, H10=0.f,H11=0.f,H12=0.f;   // m0
        float G00=0.f,G01=0.f,G02=0.f, G10=0.f,G11=0.f,G12=0.f;   // m1
        {
            const float4* v0r = (const float4*)(W_hh + (size_t)(      c0) * MEMD);
            const float4* v0z = (const float4*)(W_hh + (size_t)(100 + c0) * MEMD);
            const float4* v0n = (const float4*)(W_hh + (size_t)(200 + c0) * MEMD);
            const float4* v1r = (const float4*)(W_hh + (size_t)(      c1) * MEMD);
            const float4* v1z = (const float4*)(W_hh + (size_t)(100 + c1) * MEMD);
            const float4* v1n = (const float4*)(W_hh + (size_t)(200 + c1) * MEMD);
            #pragma unroll 2
            for (int q = 0; q < 25; q++) {
                float4 a0 = hq0[q ^ s];
                float4 a1 = hq1[q ^ s];
                float4 w;
                w = __ldg(&v0r[q]); H00 = dot4(a0, w, H00); G00 = dot4(a1, w, G00);
                w = __ldg(&v0z[q]); H01 = dot4(a0, w, H01); G01 = dot4(a1, w, G01);
                w = __ldg(&v0n[q]); H02 = dot4(a0, w, H02); G02 = dot4(a1, w, G02);
                w = __ldg(&v1r[q]); H10 = dot4(a0, w, H10); G10 = dot4(a1, w, G10);
                w = __ldg(&v1z[q]); H11 = dot4(a0, w, H11); G11 = dot4(a1, w, G11);
                w = __ldg(&v1n[q]); H12 = dot4(a0, w, H12); G12 = dot4(a1, w, G12);
            }
        }
        // epilogue
        float bir0 = __ldg(&b_ih[c0]),       bir1 = __ldg(&b_ih[c1]);
        float biz0 = __ldg(&b_ih[100 + c0]), biz1 = __ldg(&b_ih[100 + c1]);
        float bin0 = __ldg(&b_ih[200 + c0]), bin1 = __ldg(&b_ih[200 + c1]);
        float bhr0 = __ldg(&b_hh[c0]),       bhr1 = __ldg(&b_hh[c1]);
        float bhz0 = __ldg(&b_hh[100 + c0]), bhz1 = __ldg(&b_hh[100 + c1]);
        float bhn0 = __ldg(&b_hh[200 + c0]), bhn1 = __ldg(&b_hh[200 + c1]);

        auto gate = [](float ir, float iz, float inn, float hr, float hz, float hn, float h) {
            float r = 1.f / (1.f + expf(-(ir + hr)));
            float z = 1.f / (1.f + expf(-(iz + hz)));
            float n = tanhf(fmaf(r, hn, inn));
            return fmaf(z, h - n, n);     // (1-z)*n + z*h
        };
        float h00 = sh[(m0 * HSQ + ((c0 >> 2) ^ s)) * 4 + (c0 & 3)];
        float h01 = sh[(m0 * HSQ + ((c1 >> 2) ^ s)) * 4 + (c1 & 3)];
        float h10 = sh[(m1 * HSQ + ((c0 >> 2) ^ s)) * 4 + (c0 & 3)];
        float h11 = sh[(m1 * HSQ + ((c1 >> 2) ^ s)) * 4 + (c1 & 3)];

        sout[m0 * 100 + c0] = gate(A00 + bir0, A01 + biz0, A02 + bin0, H00 + bhr0, H01 + bhz0, H02 + bhn0, h00);
        sout[m0 * 100 + c1] = gate(A10 + bir1, A11 + biz1, A12 + bin1, H10 + bhr1, H11 + bhz1, H12 + bhn1, h01);
        sout[m1 * 100 + c0] = gate(B00 + bir0, B01 + biz0, B02 + bin0, G00 + bhr0, G01 + bhz0, G02 + bhn0, h10);
        sout[m1 * 100 + c1] = gate(B10 + bir1, B11 + biz1, B12 + bin1, G10 + bhr1, G11 + bhz1, G12 + bhn1, h11);
    }
    __syncthreads();

    // coalesced scatter of output rows
    for (int idx = tid; idx < TM * 100; idx += NTHREADS) {
        int m = idx / 100, c = idx - m * 100;
        out_mem[(size_t)s_node[m] * 100 + c] = sout[idx];
    }
}

// ---------------- launch ----------------
extern "C" void kernel_launch(void* const* d_in, const int* in_sizes, int n_in,
                              void* d_out, int out_size) {
    const float* memory      = (const float*)d_in[0];
    const int*   last_update = (const int*)  d_in[1];
    const int*   n_id        = (const int*)  d_in[2];
    const int*   loc_s       = (const int*)  d_in[3];
    const int*   dst_s       = (const int*)  d_in[4];
    const int*   t_s         = (const int*)  d_in[5];
    const float* raw_s       = (const float*)d_in[6];
    const int*   loc_d       = (const int*)  d_in[7];
    const int*   dst_d       = (const int*)  d_in[8];
    const int*   t_d         = (const int*)  d_in[9];
    const float* raw_d       = (const float*)d_in[10];
    const float* time_w      = (const float*)d_in[11];
    const float* time_b      = (const float*)d_in[12];
    const float* W_ih        = (const float*)d_in[13];
    const float* W_hh        = (const float*)d_in[14];
    const float* b_ih        = (const float*)d_in[15];
    const float* b_hh        = (const float*)d_in[16];

    float* out_mem = (float*)d_out;
    float* out_lu  = out_mem + (size_t)N_SEL * MEMD;
    int write_lu = (out_size >= N_SEL * MEMD + N_SEL) ? 1 : 0;

    size_t smem = (size_t)(TM * 512 + TM * 128 + TM * 100) * sizeof(float);  // ~185 KB
    cudaFuncSetAttribute(k_main, cudaFuncAttributeMaxDynamicSharedMemorySize, (int)smem);

    k_init     <<<(N_SEL + 255) / 256, 256>>>();
    k_aggregate<<<(2 * EVN + 255) / 256, 256>>>(loc_s, t_s, loc_d, t_d);
    k_partition<<<(N_SEL + 255) / 256, 256>>>();
    k_main     <<<N_SEL / TM, NTHREADS, smem>>>(memory, last_update, n_id,
                                                dst_s, raw_s, dst_d, raw_d,
                                                time_w, time_b, W_ih, W_hh, b_ih, b_hh,
                                                out_mem, out_lu, write_lu);
}

// round 6
// speedup vs baseline: 3.5459x; 3.5400x over previous
#include <cuda_runtime.h>
#include <math.h>
#include <stdint.h>

#define N_SEL 200000
#define EVN   100000
#define MEMD  100
#define RAWD  172
#define NB    128
#define NBLK  ((N_SEL + NB - 1) / NB)
#define NTHR  512

// ---- smem layout (bytes) ----
#define ASTRIDE   144                 // 36 floats per row
#define A_OFF(pb) ((pb) * 18432)      // 128 rows
#define B_OFF(pb) (36864 + (pb) * 58752)  // 408 rows
#define GID_OFF   154368
#define DST_OFF   154880
#define IDX_OFF   155392
#define VAL_OFF   155904
#define TREL_OFF  156416
#define RAWP_OFF  156928
#define SMEM_TOTAL 157952

// ---------------- small PTX helpers ----------------
__device__ __forceinline__ uint32_t smem_u32(const void* p) {
    uint32_t a;
    asm("{ .reg .u64 t; cvta.to.shared.u64 t, %1; cvt.u32.u64 %0, t; }" : "=r"(a) : "l"(p));
    return a;
}
__device__ __forceinline__ uint32_t tf32u(float x) {
    uint32_t u;
    asm("cvt.rna.tf32.f32 %0, %1;" : "=r"(u) : "f"(x));
    return u;
}
__device__ __forceinline__ void cp16(uint32_t dst, const void* src, uint32_t sz) {
    asm volatile("cp.async.cg.shared.global [%0], [%1], 16, %2;"
                 :: "r"(dst), "l"(src), "r"(sz) : "memory");
}
#define CP_COMMIT() asm volatile("cp.async.commit_group;" ::: "memory")
#define CP_WAIT0()  asm volatile("cp.async.wait_group 0;" ::: "memory")
#define CP_WAIT1()  asm volatile("cp.async.wait_group 1;" ::: "memory")

__device__ __forceinline__ void mma8(float* c, const uint32_t* a, uint32_t b0, uint32_t b1) {
    asm volatile("mma.sync.aligned.m16n8k8.row.col.f32.tf32.tf32.f32 "
                 "{%0,%1,%2,%3}, {%4,%5,%6,%7}, {%8,%9}, {%0,%1,%2,%3};"
                 : "+f"(c[0]), "+f"(c[1]), "+f"(c[2]), "+f"(c[3])
                 : "r"(a[0]), "r"(a[1]), "r"(a[2]), "r"(a[3]), "r"(b0), "r"(b1));
}

// ---------------- device scratch ----------------
__device__ unsigned long long g_win[N_SEL];
__device__ int g_cnt_valid;
__device__ int g_cnt_invalid;
__device__ int g_list[N_SEL];

// ---------------- aggregation ----------------
__global__ void k_init() {
    int i = blockIdx.x * blockDim.x + threadIdx.x;
    if (i < N_SEL) g_win[i] = 0ull;
    if (i == 0) { g_cnt_valid = 0; g_cnt_invalid = 0; }
}
__global__ void k_aggregate(const int* __restrict__ loc_s, const int* __restrict__ t_s,
                            const int* __restrict__ loc_d, const int* __restrict__ t_d) {
    int e = blockIdx.x * blockDim.x + threadIdx.x;
    if (e >= 2 * EVN) return;
    int loc, t;
    if (e < EVN) { loc = loc_s[e];       t = t_s[e]; }
    else         { loc = loc_d[e - EVN]; t = t_d[e - EVN]; }
    unsigned long long key = (((unsigned long long)(unsigned)(t + 1)) << 32) | (unsigned)e;
    atomicMax(&g_win[loc], key);
}
__global__ void k_partition() {
    int i = blockIdx.x * blockDim.x + threadIdx.x;
    if (i >= N_SEL) return;
    if (g_win[i] != 0ull) { int p = atomicAdd(&g_cnt_valid, 1);   g_list[p] = i; }
    else                  { int p = atomicAdd(&g_cnt_invalid, 1); g_list[N_SEL - 1 - p] = i; }
}

// ---------------- staging (cp.async + tenc STS) ----------------
__device__ __forceinline__ void stage_chunk(
    char* smem, uint32_t sm32, int kc, int pb, int tid,
    const float* __restrict__ memory,
    const float* __restrict__ W_ih, const float* __restrict__ W_hh,
    const float* __restrict__ time_w, const float* __restrict__ time_b,
    const int* s_gid, const int* s_dst, const float* const* s_raw,
    const float* s_trel, const int* s_val)
{
    const int q = tid & 7, cc = q * 4;
    // ---- A tile: 128 rows x 32 K ----
    #pragma unroll
    for (int mi = 0; mi < 2; mi++) {
        int m = (tid >> 3) + mi * 64;
        uint32_t dst = sm32 + A_OFF(pb) + m * ASTRIDE + q * 16;
        if (kc >= 14 && kc < 18) {          // time-encoding: compute + STS
            int col = (kc - 14) * 32 + cc;
            float4 v = make_float4(0.f, 0.f, 0.f, 0.f);
            if (s_val[m] && col < MEMD) {
                float tr = s_trel[m];
                float4 w = __ldg((const float4*)(time_w + col));
                float4 b = __ldg((const float4*)(time_b + col));
                v.x = cosf(fmaf(tr, w.x, b.x));
                v.y = cosf(fmaf(tr, w.y, b.y));
                v.z = cosf(fmaf(tr, w.z, b.z));
                v.w = cosf(fmaf(tr, w.w, b.w));
            }
            *(float4*)(smem + A_OFF(pb) + m * ASTRIDE + q * 16) = v;
        } else {
            const float* src = memory; uint32_t sz = 0;
            if (kc < 4) {
                int col = kc * 32 + cc;
                if (s_val[m] && col < MEMD) { src = memory + (size_t)s_gid[m] * MEMD + col; sz = 16; }
            } else if (kc < 8) {
                int col = (kc - 4) * 32 + cc;
                if (s_val[m] && col < MEMD) { src = memory + (size_t)s_dst[m] * MEMD + col; sz = 16; }
            } else if (kc < 14) {
                int col = (kc - 8) * 32 + cc;
                if (s_val[m] && col < RAWD) { src = s_raw[m] + col; sz = 16; }
            } else {                          // h segment
                int col = (kc - 18) * 32 + cc;
                if (col < MEMD) { src = memory + (size_t)s_gid[m] * MEMD + col; sz = 16; }
            }
            cp16(dst, src, sz);
        }
    }
    // ---- B tile: 408 rows x 32 K (virtual weight matrix) ----
    for (int w = tid >> 3; w < 408; w += 64) {
        uint32_t dst = sm32 + B_OFF(pb) + w * ASTRIDE + q * 16;
        const float* src = W_ih; uint32_t sz = 0;
        if (kc < 18) {
            if (w < 300) {
                int k0, off, wd;
                if (kc < 4)       { k0 = 0;  off = 0;   wd = 100; }
                else if (kc < 8)  { k0 = 4;  off = 100; wd = 100; }
                else if (kc < 14) { k0 = 8;  off = 200; wd = 172; }
                else              { k0 = 14; off = 372; wd = 100; }
                int sc = (kc - k0) * 32 + cc;
                if (sc < wd) { src = W_ih + (size_t)w * 472 + off + sc; sz = 16; }
            }
        } else {
            int sc = (kc - 18) * 32 + cc;
            if (sc < MEMD) {
                if (w < 200)                  { src = W_hh + (size_t)w * MEMD + sc;        sz = 16; }
                else if (w >= 300 && w < 400) { src = W_hh + (size_t)(w - 100) * MEMD + sc; sz = 16; }
            }
        }
        cp16(dst, src, sz);
    }
}

// ---------------- per-chunk MMA ----------------
__device__ __forceinline__ void compute_chunk(
    const char* smem, int pb, int wm, int wn, int g, int t,
    float (&acc)[2][13][4])
{
    const float* As = (const float*)(smem + A_OFF(pb)) + (wm * 32 + g) * 36 + t;
    const float* Bs = (const float*)(smem + B_OFF(pb)) + (wn * 100 + g) * 36 + t;
    #pragma unroll
    for (int ks = 0; ks < 4; ks++) {
        const int k0 = ks * 8;
        uint32_t a[2][4];
        #pragma unroll
        for (int mt = 0; mt < 2; mt++) {
            const float* Ap = As + mt * 16 * 36 + k0;
            a[mt][0] = tf32u(Ap[0]);
            a[mt][1] = tf32u(Ap[8 * 36]);
            a[mt][2] = tf32u(Ap[4]);
            a[mt][3] = tf32u(Ap[8 * 36 + 4]);
        }
        #pragma unroll
        for (int nt = 0; nt < 13; nt++) {
            const float* Bp = Bs + nt * 8 * 36 + k0;
            uint32_t b0 = tf32u(Bp[0]);
            uint32_t b1 = tf32u(Bp[4]);
            mma8(acc[0][nt], a[0], b0, b1);
            mma8(acc[1][nt], a[1], b0, b1);
        }
    }
}

// ---------------- main fused kernel ----------------
__global__ __launch_bounds__(NTHR, 1)
void k_main3(const float* __restrict__ memory, const int* __restrict__ last_update,
             const int* __restrict__ n_id,
             const int* __restrict__ dst_s, const float* __restrict__ raw_s,
             const int* __restrict__ dst_d, const float* __restrict__ raw_d,
             const float* __restrict__ time_w, const float* __restrict__ time_b,
             const float* __restrict__ W_ih, const float* __restrict__ W_hh,
             const float* __restrict__ b_ih, const float* __restrict__ b_hh,
             float* __restrict__ out_mem, float* __restrict__ out_lu, int write_lu)
{
    extern __shared__ __align__(128) char smem[];
    const uint32_t sm32 = smem_u32(smem);
    const int tid  = threadIdx.x;
    const int lane = tid & 31;
    const int wid  = tid >> 5;
    const int g = lane >> 2, t = lane & 3;
    const int wn = wid & 3, wm = wid >> 2;
    const int base = blockIdx.x * NB;

    int*   s_gid  = (int*)(smem + GID_OFF);
    int*   s_dst  = (int*)(smem + DST_OFF);
    int*   s_idx  = (int*)(smem + IDX_OFF);
    int*   s_val  = (int*)(smem + VAL_OFF);
    float* s_trel = (float*)(smem + TREL_OFF);
    const float** s_raw = (const float**)(smem + RAWP_OFF);

    const int nValid = g_cnt_valid;

    // ---- prologue: per-node metadata ----
    if (tid < NB) {
        int li = base + tid; if (li >= N_SEL) li = N_SEL - 1;
        int node = g_list[li];
        unsigned long long key = g_win[node];
        int gid = __ldg(&n_id[node]);
        int lu  = __ldg(&last_update[gid]);
        bool valid = (key != 0ull);
        int dst = 0, tt = 0; const float* raw = raw_s; float trel = 0.f;
        if (valid) {
            int e = (int)(key & 0xffffffffull);
            tt = (int)(key >> 32) - 1;
            if (e < EVN) { dst = __ldg(&dst_s[e]); raw = raw_s + (size_t)e * RAWD; }
            else { int e2 = e - EVN; dst = __ldg(&dst_d[e2]); raw = raw_d + (size_t)e2 * RAWD; }
            trel = (float)(tt - lu);
        }
        s_idx[tid] = node; s_gid[tid] = gid; s_dst[tid] = dst;
        s_raw[tid] = raw; s_trel[tid] = trel; s_val[tid] = valid ? 1 : 0;
        if (write_lu && base + tid < N_SEL)
            out_lu[node] = (float)(valid ? max(lu, tt) : lu);
    }
    __syncthreads();

    float acc[2][13][4];
    #pragma unroll
    for (int i = 0; i < 2; i++)
        #pragma unroll
        for (int j = 0; j < 13; j++)
            #pragma unroll
            for (int k = 0; k < 4; k++) acc[i][j][k] = 0.f;

    const int kc_start = (base < nValid) ? 0 : 18;   // all-invalid blocks: only h chunks

    stage_chunk(smem, sm32, kc_start, 0, tid, memory, W_ih, W_hh, time_w, time_b,
                s_gid, s_dst, s_raw, s_trel, s_val);
    CP_COMMIT();

    int it = 0;
    for (int kc = kc_start; kc < 22; kc++, it++) {
        if (kc + 1 < 22) {
            stage_chunk(smem, sm32, kc + 1, (it + 1) & 1, tid, memory, W_ih, W_hh,
                        time_w, time_b, s_gid, s_dst, s_raw, s_trel, s_val);
            CP_COMMIT();
            CP_WAIT1();
        } else {
            CP_WAIT0();
        }
        __syncthreads();
        compute_chunk(smem, it & 1, wm, wn, g, t, acc);
        __syncthreads();
    }

    // ---- epilogue: two 64-row passes through smem, GRU gates, write out ----
    float* Dp = (float*)smem;                 // 64 x 404 f32, reuses A/B buffers
    #pragma unroll
    for (int p = 0; p < 2; p++) {
        if ((wm >> 1) == p) {
            #pragma unroll
            for (int mt = 0; mt < 2; mt++) {
                int r0 = (wm & 1) * 32 + mt * 16 + g;
                #pragma unroll
                for (int nt = 0; nt < 13; nt++) {
                    int c = wn * 100 + nt * 8 + 2 * t;
                    Dp[r0 * 404 + c]           = acc[mt][nt][0];
                    Dp[r0 * 404 + c + 1]       = acc[mt][nt][1];
                    Dp[(r0 + 8) * 404 + c]     = acc[mt][nt][2];
                    Dp[(r0 + 8) * 404 + c + 1] = acc[mt][nt][3];
                }
            }
        }
        __syncthreads();
        for (int idx = tid; idx < 64 * MEMD; idx += NTHR) {
            int ml = idx / MEMD, c = idx - ml * MEMD;
            int m = p * 64 + ml;
            float r = Dp[ml * 404 + c]       + __ldg(&b_ih[c])       + __ldg(&b_hh[c]);
            float z = Dp[ml * 404 + 100 + c] + __ldg(&b_ih[100 + c]) + __ldg(&b_hh[100 + c]);
            r = 1.f / (1.f + expf(-r));
            z = 1.f / (1.f + expf(-z));
            float hn = Dp[ml * 404 + 300 + c] + __ldg(&b_hh[200 + c]);
            float n = tanhf(Dp[ml * 404 + 200 + c] + __ldg(&b_ih[200 + c]) + r * hn);
            float h = __ldg(memory + (size_t)s_gid[m] * MEMD + c);
            out_mem[(size_t)s_idx[m] * MEMD + c] = fmaf(z, h - n, n);
        }
        __syncthreads();
    }
}

// ---------------- launch ----------------
extern "C" void kernel_launch(void* const* d_in, const int* in_sizes, int n_in,
                              void* d_out, int out_size) {
    const float* memory      = (const float*)d_in[0];
    const int*   last_update = (const int*)  d_in[1];
    const int*   n_id        = (const int*)  d_in[2];
    const int*   loc_s       = (const int*)  d_in[3];
    const int*   dst_s       = (const int*)  d_in[4];
    const int*   t_s         = (const int*)  d_in[5];
    const float* raw_s       = (const float*)d_in[6];
    const int*   loc_d       = (const int*)  d_in[7];
    const int*   dst_d       = (const int*)  d_in[8];
    const int*   t_d         = (const int*)  d_in[9];
    const float* raw_d       = (const float*)d_in[10];
    const float* time_w      = (const float*)d_in[11];
    const float* time_b      = (const float*)d_in[12];
    const float* W_ih        = (const float*)d_in[13];
    const float* W_hh        = (const float*)d_in[14];
    const float* b_ih        = (const float*)d_in[15];
    const float* b_hh        = (const float*)d_in[16];

    float* out_mem = (float*)d_out;
    float* out_lu  = out_mem + (size_t)N_SEL * MEMD;
    int write_lu = (out_size >= N_SEL * MEMD + N_SEL) ? 1 : 0;

    cudaFuncSetAttribute(k_main3, cudaFuncAttributeMaxDynamicSharedMemorySize, SMEM_TOTAL);

    k_init     <<<(N_SEL + 255) / 256, 256>>>();
    k_aggregate<<<(2 * EVN + 255) / 256, 256>>>(loc_s, t_s, loc_d, t_d);
    k_partition<<<(N_SEL + 255) / 256, 256>>>();
    k_main3    <<<NBLK, NTHR, SMEM_TOTAL>>>(memory, last_update, n_id,
                                            dst_s, raw_s, dst_d, raw_d,
                                            time_w, time_b, W_ih, W_hh, b_ih, b_hh,
                                            out_mem, out_lu, write_lu);
}

// round 7
// speedup vs baseline: 4.6843x; 1.3210x over previous
#include <cuda_runtime.h>
#include <math.h>
#include <stdint.h>

#define N_SEL 200000
#define EVN   100000
#define MEMD  100
#define RAWD  172
#define NB    128
#define NBLK  ((N_SEL + NB - 1) / NB)
#define NTHR  512
#define KCH   18            // 18 K-chunks of 32: cols [0,576), real K = 572
#define BROWS 408           // 400 weight rows + 8 zero pad

// ---- smem layout (bytes) ----
#define ASTRIDE   144                 // 36 floats per row
#define A_OFF(pb) ((pb) * 18432)      // 128 rows
#define B_OFF(pb) (36864 + (pb) * 58752)  // 408 rows
#define GID_OFF   154368
#define DST_OFF   154880
#define IDX_OFF   155392
#define VAL_OFF   155904
#define TREL_OFF  156416
#define RAWP_OFF  156928
#define SMEM_TOTAL 157952

// ---------------- small PTX helpers ----------------
__device__ __forceinline__ uint32_t smem_u32(const void* p) {
    uint32_t a;
    asm("{ .reg .u64 t; cvta.to.shared.u64 t, %1; cvt.u32.u64 %0, t; }" : "=r"(a) : "l"(p));
    return a;
}
__device__ __forceinline__ uint32_t tf32u(float x) {
    uint32_t u;
    asm("cvt.rna.tf32.f32 %0, %1;" : "=r"(u) : "f"(x));
    return u;
}
__device__ __forceinline__ void cp16(uint32_t dst, const void* src, uint32_t sz) {
    asm volatile("cp.async.cg.shared.global [%0], [%1], 16, %2;"
                 :: "r"(dst), "l"(src), "r"(sz) : "memory");
}
#define CP_COMMIT() asm volatile("cp.async.commit_group;" ::: "memory")
#define CP_WAIT0()  asm volatile("cp.async.wait_group 0;" ::: "memory")
#define CP_WAIT1()  asm volatile("cp.async.wait_group 1;" ::: "memory")

__device__ __forceinline__ void mma8(float* c, const uint32_t* a, uint32_t b0, uint32_t b1) {
    asm volatile("mma.sync.aligned.m16n8k8.row.col.f32.tf32.tf32.f32 "
                 "{%0,%1,%2,%3}, {%4,%5,%6,%7}, {%8,%9}, {%0,%1,%2,%3};"
                 : "+f"(c[0]), "+f"(c[1]), "+f"(c[2]), "+f"(c[3])
                 : "r"(a[0]), "r"(a[1]), "r"(a[2]), "r"(a[3]), "r"(b0), "r"(b1));
}

// ---------------- device scratch ----------------
__device__ unsigned long long g_win[N_SEL];
__device__ int g_cnt_valid;
__device__ int g_cnt_invalid;
__device__ int g_list[N_SEL];
__device__ float g_Bpk[BROWS * 576];   // prepacked tf32-rounded virtual weight matrix

// ---------------- aggregation ----------------
__global__ void k_init() {
    int i = blockIdx.x * blockDim.x + threadIdx.x;
    if (i < N_SEL) g_win[i] = 0ull;
    if (i == 0) { g_cnt_valid = 0; g_cnt_invalid = 0; }
}
__global__ void k_aggregate(const int* __restrict__ loc_s, const int* __restrict__ t_s,
                            const int* __restrict__ loc_d, const int* __restrict__ t_d) {
    int e = blockIdx.x * blockDim.x + threadIdx.x;
    if (e >= 2 * EVN) return;
    int loc, t;
    if (e < EVN) { loc = loc_s[e];       t = t_s[e]; }
    else         { loc = loc_d[e - EVN]; t = t_d[e - EVN]; }
    unsigned long long key = (((unsigned long long)(unsigned)(t + 1)) << 32) | (unsigned)e;
    atomicMax(&g_win[loc], key);
}
__global__ void k_partition() {
    int i = blockIdx.x * blockDim.x + threadIdx.x;
    if (i >= N_SEL) return;
    if (g_win[i] != 0ull) { int p = atomicAdd(&g_cnt_valid, 1);   g_list[p] = i; }
    else                  { int p = atomicAdd(&g_cnt_invalid, 1); g_list[N_SEL - 1 - p] = i; }
}

// ---------------- weight prepack: virtual B [408 x 576], tf32-rounded ----------------
// B row r, col c:
//   r in [0,200):  c<472 -> W_ih[r][c]        ; c in [472,572) -> W_hh[r][c-472]
//   r in [200,300): c<472 -> W_ih[r][c] (i_n) ; else 0
//   r in [300,400): c in [472,572) -> W_hh[r-100][c-472] (h_n) ; else 0
//   r >= 400 or c >= 572: 0
__global__ void k_prepack(const float* __restrict__ W_ih, const float* __restrict__ W_hh) {
    int idx = blockIdx.x * blockDim.x + threadIdx.x;
    if (idx >= BROWS * 576) return;
    int r = idx / 576, c = idx - r * 576;
    float v = 0.f;
    if (r < 200) {
        if (c < 472) v = __ldg(&W_ih[(size_t)r * 472 + c]);
        else if (c < 572) v = __ldg(&W_hh[(size_t)r * MEMD + (c - 472)]);
    } else if (r < 300) {
        if (c < 472) v = __ldg(&W_ih[(size_t)r * 472 + c]);
    } else if (r < 400) {
        if (c >= 472 && c < 572) v = __ldg(&W_hh[(size_t)(r - 100) * MEMD + (c - 472)]);
    }
    g_Bpk[idx] = __uint_as_float(tf32u(v));
}

// ---------------- staging ----------------
__device__ __forceinline__ void stage_chunk(
    char* smem, uint32_t sm32, int kc, int pb, int tid,
    const float* __restrict__ memory,
    const float* __restrict__ time_w, const float* __restrict__ time_b,
    const int* s_gid, const int* s_dst, const float* const* s_raw,
    const float* s_trel, const int* s_val)
{
    const int q = tid & 7;
    const int c4 = kc * 32 + q * 4;      // global A column of this lane's float4
    // ---- A tile: 128 rows x 32 K ----
    #pragma unroll
    for (int mi = 0; mi < 2; mi++) {
        int m = (tid >> 3) + mi * 64;
        uint32_t dst = sm32 + A_OFF(pb) + m * ASTRIDE + q * 16;
        bool val = (s_val[m] != 0);
        if (c4 >= 372 && c4 < 472) {       // time-encoding: compute + STS
            float4 v = make_float4(0.f, 0.f, 0.f, 0.f);
            if (val) {
                int col = c4 - 372;
                float tr = s_trel[m];
                float4 w = __ldg((const float4*)(time_w + col));
                float4 b = __ldg((const float4*)(time_b + col));
                v.x = cosf(fmaf(tr, w.x, b.x));
                v.y = cosf(fmaf(tr, w.y, b.y));
                v.z = cosf(fmaf(tr, w.z, b.z));
                v.w = cosf(fmaf(tr, w.w, b.w));
            }
            *(float4*)(smem + A_OFF(pb) + m * ASTRIDE + q * 16) = v;
        } else {
            const float* src = memory; uint32_t sz = 0;
            if (c4 < 100)        { if (val) { src = memory + (size_t)s_gid[m] * MEMD + c4;          sz = 16; } }
            else if (c4 < 200)   { if (val) { src = memory + (size_t)s_dst[m] * MEMD + (c4 - 100);  sz = 16; } }
            else if (c4 < 372)   { if (val) { src = s_raw[m] + (c4 - 200);                           sz = 16; } }
            else if (c4 < 572)   { src = memory + (size_t)s_gid[m] * MEMD + (c4 - 472);              sz = 16; }
            cp16(dst, src, sz);  // sz=0 -> zero-fill (invalid rows / pad cols)
        }
    }
    // ---- B tile: dense copy from prepacked buffer ----
    const float* Bsrc = g_Bpk + kc * 32 + q * 4;
    for (int w = tid >> 3; w < BROWS; w += 64)
        cp16(sm32 + B_OFF(pb) + w * ASTRIDE + q * 16, Bsrc + (size_t)w * 576, 16);
}

// ---------------- per-chunk MMA (B pre-converted; only A needs cvt) ----------------
__device__ __forceinline__ void compute_chunk(
    const char* smem, int pb, int wm, int wn, int g, int t,
    float (&acc)[2][13][4])
{
    const float*    As = (const float*)(smem + A_OFF(pb)) + (wm * 32 + g) * 36 + t;
    const uint32_t* Bs = (const uint32_t*)(smem + B_OFF(pb)) + (wn * 100 + g) * 36 + t;
    #pragma unroll
    for (int ks = 0; ks < 4; ks++) {
        const int k0 = ks * 8;
        uint32_t a[2][4];
        #pragma unroll
        for (int mt = 0; mt < 2; mt++) {
            const float* Ap = As + mt * 16 * 36 + k0;
            a[mt][0] = tf32u(Ap[0]);
            a[mt][1] = tf32u(Ap[8 * 36]);
            a[mt][2] = tf32u(Ap[4]);
            a[mt][3] = tf32u(Ap[8 * 36 + 4]);
        }
        #pragma unroll
        for (int nt = 0; nt < 13; nt++) {
            const uint32_t* Bp = Bs + nt * 8 * 36 + k0;
            uint32_t b0 = Bp[0];
            uint32_t b1 = Bp[4];
            mma8(acc[0][nt], a[0], b0, b1);
            mma8(acc[1][nt], a[1], b0, b1);
        }
    }
}

// ---------------- main fused kernel ----------------
__global__ __launch_bounds__(NTHR, 1)
void k_main3(const float* __restrict__ memory, const int* __restrict__ last_update,
             const int* __restrict__ n_id,
             const int* __restrict__ dst_s, const float* __restrict__ raw_s,
             const int* __restrict__ dst_d, const float* __restrict__ raw_d,
             const float* __restrict__ time_w, const float* __restrict__ time_b,
             const float* __restrict__ b_ih, const float* __restrict__ b_hh,
             float* __restrict__ out_mem, float* __restrict__ out_lu, int write_lu)
{
    extern __shared__ __align__(128) char smem[];
    const uint32_t sm32 = smem_u32(smem);
    const int tid  = threadIdx.x;
    const int lane = tid & 31;
    const int wid  = tid >> 5;
    const int g = lane >> 2, t = lane & 3;
    const int wn = wid & 3, wm = wid >> 2;
    const int base = blockIdx.x * NB;

    int*   s_gid  = (int*)(smem + GID_OFF);
    int*   s_dst  = (int*)(smem + DST_OFF);
    int*   s_idx  = (int*)(smem + IDX_OFF);
    int*   s_val  = (int*)(smem + VAL_OFF);
    float* s_trel = (float*)(smem + TREL_OFF);
    const float** s_raw = (const float**)(smem + RAWP_OFF);

    const int nValid = g_cnt_valid;

    // ---- prologue: per-node metadata ----
    if (tid < NB) {
        int li = base + tid; if (li >= N_SEL) li = N_SEL - 1;
        int node = g_list[li];
        unsigned long long key = g_win[node];
        int gid = __ldg(&n_id[node]);
        int lu  = __ldg(&last_update[gid]);
        bool valid = (key != 0ull);
        int dst = 0, tt = 0; const float* raw = raw_s; float trel = 0.f;
        if (valid) {
            int e = (int)(key & 0xffffffffull);
            tt = (int)(key >> 32) - 1;
            if (e < EVN) { dst = __ldg(&dst_s[e]); raw = raw_s + (size_t)e * RAWD; }
            else { int e2 = e - EVN; dst = __ldg(&dst_d[e2]); raw = raw_d + (size_t)e2 * RAWD; }
            trel = (float)(tt - lu);
        }
        s_idx[tid] = node; s_gid[tid] = gid; s_dst[tid] = dst;
        s_raw[tid] = raw; s_trel[tid] = trel; s_val[tid] = valid ? 1 : 0;
        if (write_lu && base + tid < N_SEL)
            out_lu[node] = (float)(valid ? max(lu, tt) : lu);
    }
    __syncthreads();

    float acc[2][13][4];
    #pragma unroll
    for (int i = 0; i < 2; i++)
        #pragma unroll
        for (int j = 0; j < 13; j++)
            #pragma unroll
            for (int k = 0; k < 4; k++) acc[i][j][k] = 0.f;

    // all-invalid blocks only need cols >= 448 (tenc cols are zero there anyway)
    const int kc_start = (base < nValid) ? 0 : 14;

    stage_chunk(smem, sm32, kc_start, 0, tid, memory, time_w, time_b,
                s_gid, s_dst, s_raw, s_trel, s_val);
    CP_COMMIT();

    int it = 0;
    for (int kc = kc_start; kc < KCH; kc++, it++) {
        if (kc + 1 < KCH) {
            stage_chunk(smem, sm32, kc + 1, (it + 1) & 1, tid, memory,
                        time_w, time_b, s_gid, s_dst, s_raw, s_trel, s_val);
            CP_COMMIT();
            CP_WAIT1();
        } else {
            CP_WAIT0();
        }
        __syncthreads();
        compute_chunk(smem, it & 1, wm, wn, g, t, acc);
        __syncthreads();
    }

    // ---- epilogue: two 64-row passes through smem, GRU gates, write out ----
    float* Dp = (float*)smem;                 // 64 x 404 f32, reuses A/B buffers
    #pragma unroll
    for (int p = 0; p < 2; p++) {
        if ((wm >> 1) == p) {
            #pragma unroll
            for (int mt = 0; mt < 2; mt++) {
                int r0 = (wm & 1) * 32 + mt * 16 + g;
                #pragma unroll
                for (int nt = 0; nt < 13; nt++) {
                    int c = wn * 100 + nt * 8 + 2 * t;
                    Dp[r0 * 404 + c]           = acc[mt][nt][0];
                    Dp[r0 * 404 + c + 1]       = acc[mt][nt][1];
                    Dp[(r0 + 8) * 404 + c]     = acc[mt][nt][2];
                    Dp[(r0 + 8) * 404 + c + 1] = acc[mt][nt][3];
                }
            }
        }
        __syncthreads();
        for (int idx = tid; idx < 64 * MEMD; idx += NTHR) {
            int ml = idx / MEMD, c = idx - ml * MEMD;
            int m = p * 64 + ml;
            float r = Dp[ml * 404 + c]       + __ldg(&b_ih[c])       + __ldg(&b_hh[c]);
            float z = Dp[ml * 404 + 100 + c] + __ldg(&b_ih[100 + c]) + __ldg(&b_hh[100 + c]);
            r = 1.f / (1.f + expf(-r));
            z = 1.f / (1.f + expf(-z));
            float hn = Dp[ml * 404 + 300 + c] + __ldg(&b_hh[200 + c]);
            float n = tanhf(Dp[ml * 404 + 200 + c] + __ldg(&b_ih[200 + c]) + r * hn);
            float h = __ldg(memory + (size_t)s_gid[m] * MEMD + c);
            out_mem[(size_t)s_idx[m] * MEMD + c] = fmaf(z, h - n, n);
        }
        __syncthreads();
    }
}

// ---------------- launch ----------------
extern "C" void kernel_launch(void* const* d_in, const int* in_sizes, int n_in,
                              void* d_out, int out_size) {
    const float* memory      = (const float*)d_in[0];
    const int*   last_update = (const int*)  d_in[1];
    const int*   n_id        = (const int*)  d_in[2];
    const int*   loc_s       = (const int*)  d_in[3];
    const int*   dst_s       = (const int*)  d_in[4];
    const int*   t_s         = (const int*)  d_in[5];
    const float* raw_s       = (const float*)d_in[6];
    const int*   loc_d       = (const int*)  d_in[7];
    const int*   dst_d       = (const int*)  d_in[8];
    const int*   t_d         = (const int*)  d_in[9];
    const float* raw_d       = (const float*)d_in[10];
    const float* time_w      = (const float*)d_in[11];
    const float* time_b      = (const float*)d_in[12];
    const float* W_ih        = (const float*)d_in[13];
    const float* W_hh        = (const float*)d_in[14];
    const float* b_ih        = (const float*)d_in[15];
    const float* b_hh        = (const float*)d_in[16];

    float* out_mem = (float*)d_out;
    float* out_lu  = out_mem + (size_t)N_SEL * MEMD;
    int write_lu = (out_size >= N_SEL * MEMD + N_SEL) ? 1 : 0;

    cudaFuncSetAttribute(k_main3, cudaFuncAttributeMaxDynamicSharedMemorySize, SMEM_TOTAL);

    k_init     <<<(N_SEL + 255) / 256, 256>>>();
    k_aggregate<<<(2 * EVN + 255) / 256, 256>>>(loc_s, t_s, loc_d, t_d);
    k_partition<<<(N_SEL + 255) / 256, 256>>>();
    k_prepack  <<<(BROWS * 576 + 255) / 256, 256>>>(W_ih, W_hh);
    k_main3    <<<NBLK, NTHR, SMEM_TOTAL>>>(memory, last_update, n_id,
                                            dst_s, raw_s, dst_d, raw_d,
                                            time_w, time_b, b_ih, b_hh,
                                            out_mem, out_lu, write_lu);
}